// round 2
// baseline (speedup 1.0000x reference)
#include <cuda_runtime.h>
#include <cstdint>

// ---------------- problem constants ----------------
#define B_      128
#define T_IN_   240
#define T_OUT_  30
#define D_      128
#define H_      256
#define G3_     768

#define ENC_LEN 30720   // T_IN * B
#define DEC_LEN 3840    // T_OUT * B

// segmentation of the serial chains
#define NSEG_ENC 32
#define NSEG_DEC 4
#define CHUNK    960     // 32*960 = 30720, 4*960 = 3840
#define WARMUP   448

// ---------------- device scratch (allowed: __device__ globals) ----------------
__device__ float g_gi_enc[(size_t)ENC_LEN * G3_];   // ~94 MB
__device__ float g_gi_dec[(size_t)DEC_LEN * G3_];   // ~12 MB

// ---------------- helpers ----------------
__device__ __forceinline__ uint32_t smem_u32(const void* p) {
    return (uint32_t)__cvta_generic_to_shared(p);
}
__device__ __forceinline__ uint32_t mapa_u32(uint32_t addr, uint32_t rank) {
    uint32_t d;
    asm("mapa.shared::cluster.u32 %0, %1, %2;" : "=r"(d) : "r"(addr), "r"(rank));
    return d;
}
__device__ __forceinline__ void st_remote_f32(uint32_t addr, float v) {
    asm volatile("st.shared::cluster.f32 [%0], %1;" :: "r"(addr), "f"(v) : "memory");
}
__device__ __forceinline__ void cl_sync() {
    asm volatile("barrier.cluster.arrive.aligned;" ::: "memory");
    asm volatile("barrier.cluster.wait.aligned;"   ::: "memory");
}
__device__ __forceinline__ float sig_(float x) { return 1.0f / (1.0f + __expf(-x)); }
__device__ __forceinline__ float th_(float x)  { return 2.0f / (1.0f + __expf(-2.0f * x)) - 1.0f; }

// ============================================================
// Phase 1: GI = X @ Wih^T + bih, for encoder (all 30720 rows)
// and decoder (3840 strided rows). 64x64 tiles, BK=64, 256 thr.
// grid.x: 0..479 enc position-tiles, 480..539 dec; grid.y: 12 gate tiles
// ============================================================
__global__ __launch_bounds__(256)
void gi_gemm(const float* __restrict__ x,
             const float* __restrict__ Wih_e, const float* __restrict__ bih_e,
             const float* __restrict__ Wih_d, const float* __restrict__ bih_d)
{
    __shared__ float Xs[64][68];   // [k][pos]
    __shared__ float Ws[64][68];   // [k][gate]

    const int tileP = blockIdx.x;
    const bool enc = (tileP < (ENC_LEN / 64));
    const float* __restrict__ Wih = enc ? Wih_e : Wih_d;
    const float* __restrict__ bih = enc ? bih_e : bih_d;
    float* __restrict__ gout = enc ? g_gi_enc : g_gi_dec;
    const int p0 = (enc ? tileP : (tileP - ENC_LEN / 64)) * 64;
    const int g0 = blockIdx.y * 64;
    const int tid = threadIdx.x;
    const int tstride = enc ? 1 : 8;

    const int tx = tid & 15;      // gate micro index
    const int ty = tid >> 4;      // pos  micro index
    float acc[4][4] = {};

    for (int kc = 0; kc < 2; ++kc) {
        // load X tile: 64 positions x 64 k
        #pragma unroll
        for (int i = tid; i < 64 * 64; i += 256) {
            int pos = i >> 6, k = i & 63;
            int p = p0 + pos;
            int b = p & 127, t = (p >> 7) * tstride;
            Xs[k][pos] = x[((size_t)b * T_IN_ + t) * D_ + kc * 64 + k];
        }
        // load W tile: 64 gates x 64 k
        #pragma unroll
        for (int i = tid; i < 64 * 64; i += 256) {
            int g = i >> 6, k = i & 63;
            Ws[k][g] = Wih[(size_t)(g0 + g) * D_ + kc * 64 + k];
        }
        __syncthreads();

        #pragma unroll 16
        for (int k = 0; k < 64; ++k) {
            float4 a = *(const float4*)&Xs[k][ty * 4];
            float4 b = *(const float4*)&Ws[k][tx * 4];
            float av[4] = {a.x, a.y, a.z, a.w};
            float bv[4] = {b.x, b.y, b.z, b.w};
            #pragma unroll
            for (int i = 0; i < 4; ++i)
                #pragma unroll
                for (int j = 0; j < 4; ++j)
                    acc[i][j] = fmaf(av[i], bv[j], acc[i][j]);
        }
        __syncthreads();
    }

    float bz[4];
    #pragma unroll
    for (int j = 0; j < 4; ++j) bz[j] = bih[g0 + tx * 4 + j];

    #pragma unroll
    for (int i = 0; i < 4; ++i) {
        int p = p0 + ty * 4 + i;
        float4 o;
        o.x = acc[i][0] + bz[0];
        o.y = acc[i][1] + bz[1];
        o.z = acc[i][2] + bz[2];
        o.w = acc[i][3] + bz[3];
        *(float4*)&gout[(size_t)p * G3_ + g0 + tx * 4] = o;
    }
}

// ============================================================
// Phase 2: segmented GRU scan. One segment = one 4-CTA cluster.
// CTA rank c owns H-coords [c*64, c*64+64) -> 192 gh rows (3 gates).
// Whh slice transposed in SMEM: WT2[k2][gr] (float2 along k).
// h double-buffered, broadcast each step via st.shared::cluster,
// one barrier.cluster per step.
// ============================================================
#define SMEM_SCAN_BYTES ((128 * 192 * 2 + 2 * 256 + 3 * 192) * 4)  // 200960

__global__ __launch_bounds__(256) __cluster_dims__(4, 1, 1)
void gru_scan(const float* __restrict__ Whh_e, const float* __restrict__ bhh_e,
              const float* __restrict__ Whh_d, const float* __restrict__ bhh_d,
              float* __restrict__ out)
{
    extern __shared__ float smem[];
    float2* WT2  = (float2*)smem;              // [128][192] float2
    float* hbuf0 = smem + 128 * 192 * 2;       // 256
    float* hbuf1 = hbuf0 + 256;                // 256
    float* sGH   = hbuf1 + 256;                // 192
    float* sGI   = sGH + 192;                  // 192
    float* bh    = sGI + 192;                  // 192

    const int tid = threadIdx.x;
    uint32_t rank;
    asm("mov.u32 %0, %%cluster_ctarank;" : "=r"(rank));

    const int seg  = blockIdx.x >> 2;
    const bool enc = seg < NSEG_ENC;
    const int lseg = enc ? seg : seg - NSEG_ENC;
    const float* __restrict__ Whh = enc ? Whh_e : Whh_d;
    const float* __restrict__ bhh = enc ? bhh_e : bhh_d;
    const float* __restrict__ gi  = enc ? g_gi_enc : g_gi_dec;

    const int out_begin = lseg * CHUNK;
    const int out_end   = out_begin + CHUNK;
    int start = out_begin - WARMUP;
    if (start < 0) start = 0;

    // ---- load transposed Whh slice ----
    // gr = gate*64 + jl ; global row R = gate*256 + rank*64 + jl
    for (int i = tid; i < 192 * 128; i += 256) {
        int gr = i >> 7, k2 = i & 127;
        int gate = gr >> 6, jl = gr & 63;
        int R = gate * 256 + (int)rank * 64 + jl;
        const float* wrow = Whh + (size_t)R * H_ + k2 * 2;
        WT2[k2 * 192 + gr] = make_float2(wrow[0], wrow[1]);
    }
    if (tid < 192) {
        int gate = tid >> 6, jl = tid & 63;
        bh[tid] = bhh[gate * 256 + (int)rank * 64 + jl];
    }
    hbuf0[tid] = 0.0f;
    hbuf1[tid] = 0.0f;
    __syncthreads();
    cl_sync();   // all CTAs ready before remote writes begin

    // peer addresses of both h buffers
    uint32_t my_h0 = smem_u32(hbuf0);
    uint32_t my_h1 = smem_u32(hbuf1);
    uint32_t peer_h0[4], peer_h1[4];
    #pragma unroll
    for (int r = 0; r < 4; ++r) {
        peer_h0[r] = mapa_u32(my_h0, r);
        peer_h1[r] = mapa_u32(my_h1, r);
    }

    const int gate_t = tid >> 6;          // for tid<192: gate index
    const int jl_t   = tid & 63;
    const size_t gi_off = (size_t)gate_t * 256 + rank * 64 + jl_t;

    for (int p = start; p < out_end; ++p) {
        const int par = (p - start) & 1;
        const float* hr = par ? hbuf1 : hbuf0;
        const uint32_t* wpeers = par ? peer_h0 : peer_h1;

        if (tid < 192) {
            // input-projection value for this step (latency hidden by matvec)
            float giv = gi[(size_t)p * G3_ + gi_off];

            float acc = 0.0f;
            const float4* h4 = (const float4*)hr;
            const float2* wp = WT2 + tid;
            #pragma unroll 16
            for (int i = 0; i < 64; ++i) {
                float4 hv = h4[i];
                float2 wa = wp[(2 * i) * 192];
                float2 wb = wp[(2 * i + 1) * 192];
                acc = fmaf(wa.x, hv.x, acc);
                acc = fmaf(wa.y, hv.y, acc);
                acc = fmaf(wb.x, hv.z, acc);
                acc = fmaf(wb.y, hv.w, acc);
            }
            sGH[tid] = acc + bh[tid];
            sGI[tid] = giv;
        }
        __syncthreads();

        if (tid < 64) {
            float r_ = sig_(sGI[tid]       + sGH[tid]);
            float z_ = sig_(sGI[64 + tid]  + sGH[64 + tid]);
            float n_ = th_ (sGI[128 + tid] + r_ * sGH[128 + tid]);
            float hold = hr[(int)rank * 64 + tid];
            float hn = (1.0f - z_) * n_ + z_ * hold;

            // broadcast my h' coord to all 4 CTAs' write buffer
            uint32_t off = ((uint32_t)rank * 64 + (uint32_t)tid) * 4;
            #pragma unroll
            for (int r = 0; r < 4; ++r) st_remote_f32(wpeers[r] + off, hn);

            // outputs
            if (p >= out_begin) {
                if (enc) {
                    if ((p & 127) == 127) {
                        int t_out = p >> 7;
                        out[(size_t)t_out * H_ + rank * 64 + tid] = hn;
                    }
                } else {
                    int b = p & 127, t = p >> 7;
                    out[(size_t)(T_IN_ * H_) + ((size_t)b * T_OUT_ + t) * H_ + rank * 64 + tid] = hn;
                }
            }
        }
        cl_sync();   // publishes h' (release) / acquires peers' writes
    }
}

// ============================================================
// launch
// ============================================================
extern "C" void kernel_launch(void* const* d_in, const int* in_sizes, int n_in,
                              void* d_out, int out_size)
{
    const float* x     = (const float*)d_in[0];
    const float* Wih_e = (const float*)d_in[1];
    const float* Whh_e = (const float*)d_in[2];
    const float* bih_e = (const float*)d_in[3];
    const float* bhh_e = (const float*)d_in[4];
    const float* Wih_d = (const float*)d_in[5];
    const float* Whh_d = (const float*)d_in[6];
    const float* bih_d = (const float*)d_in[7];
    const float* bhh_d = (const float*)d_in[8];
    float* out = (float*)d_out;

    cudaFuncSetAttribute(gru_scan, cudaFuncAttributeMaxDynamicSharedMemorySize,
                         SMEM_SCAN_BYTES);

    dim3 ggrid(ENC_LEN / 64 + DEC_LEN / 64, G3_ / 64);  // (540, 12)
    gi_gemm<<<ggrid, 256>>>(x, Wih_e, bih_e, Wih_d, bih_d);

    gru_scan<<<(NSEG_ENC + NSEG_DEC) * 4, 256, SMEM_SCAN_BYTES>>>(
        Whh_e, bhh_e, Whh_d, bhh_d, out);
}

// round 3
// speedup vs baseline: 1.5921x; 1.5921x over previous
#include <cuda_runtime.h>
#include <cstdint>

// ---------------- problem constants ----------------
#define B_      128
#define T_IN_   240
#define T_OUT_  30
#define D_      128
#define H_      256
#define G3_     768

#define ENC_LEN 30720   // T_IN * B
#define DEC_LEN 3840    // T_OUT * B

// segmentation of the serial chains
#define NSEG_ENC 32
#define NSEG_DEC 4
#define CHUNK    960     // 32*960 = 30720, 4*960 = 3840
#define WARMUP   320

// ---------------- device scratch ----------------
__device__ float g_gi_enc[(size_t)ENC_LEN * G3_];   // ~94 MB
__device__ float g_gi_dec[(size_t)DEC_LEN * G3_];   // ~12 MB

// ---------------- helpers ----------------
__device__ __forceinline__ uint32_t smem_u32(const void* p) {
    return (uint32_t)__cvta_generic_to_shared(p);
}
__device__ __forceinline__ uint32_t mapa_u32(uint32_t addr, uint32_t rank) {
    uint32_t d;
    asm("mapa.shared::cluster.u32 %0, %1, %2;" : "=r"(d) : "r"(addr), "r"(rank));
    return d;
}
__device__ __forceinline__ void cl_sync() {
    asm volatile("barrier.cluster.arrive.aligned;" ::: "memory");
    asm volatile("barrier.cluster.wait.aligned;"   ::: "memory");
}
__device__ __forceinline__ void mbar_init(uint32_t mbar, uint32_t count) {
    asm volatile("mbarrier.init.shared.b64 [%0], %1;" :: "r"(mbar), "r"(count) : "memory");
}
__device__ __forceinline__ void mbar_arrive_expect(uint32_t mbar, uint32_t bytes) {
    asm volatile("mbarrier.arrive.expect_tx.shared::cta.b64 _, [%0], %1;"
                 :: "r"(mbar), "r"(bytes) : "memory");
}
__device__ __forceinline__ void mbar_wait_parity(uint32_t mbar, uint32_t parity) {
    uint32_t done;
    asm volatile(
        "{\n\t.reg .pred p;\n\t"
        "mbarrier.try_wait.parity.acquire.cta.shared::cta.b64 p, [%1], %2;\n\t"
        "selp.b32 %0, 1, 0, p;\n\t}"
        : "=r"(done) : "r"(mbar), "r"(parity) : "memory");
    if (!done) {
        asm volatile(
            "{\n\t.reg .pred P1;\n\t"
            "WAIT_LOOP_%=:\n\t"
            "mbarrier.try_wait.parity.acquire.cta.shared::cta.b64 P1, [%0], %1, 0x989680;\n\t"
            "@P1 bra.uni WAIT_DONE_%=;\n\t"
            "bra.uni WAIT_LOOP_%=;\n\t"
            "WAIT_DONE_%=:\n\t}"
            :: "r"(mbar), "r"(parity) : "memory");
    }
}
__device__ __forceinline__ void st_async_f32(uint32_t addr, float v, uint32_t mbar) {
    asm volatile(
        "st.async.weak.shared::cluster.mbarrier::complete_tx::bytes.f32 [%0], %1, [%2];"
        :: "r"(addr), "f"(v), "r"(mbar) : "memory");
}
__device__ __forceinline__ unsigned long long ffma2(unsigned long long a,
                                                    unsigned long long b,
                                                    unsigned long long c) {
    unsigned long long r;
    asm("fma.rn.f32x2 %0, %1, %2, %3;" : "=l"(r) : "l"(a), "l"(b), "l"(c));
    return r;
}
__device__ __forceinline__ float sig_(float x) { return 1.0f / (1.0f + __expf(-x)); }
__device__ __forceinline__ float th_(float x)  { return 2.0f / (1.0f + __expf(-2.0f * x)) - 1.0f; }

// ============================================================
// Phase 1: GI = X @ Wih^T + bih  (unchanged — verified)
// ============================================================
__global__ __launch_bounds__(256)
void gi_gemm(const float* __restrict__ x,
             const float* __restrict__ Wih_e, const float* __restrict__ bih_e,
             const float* __restrict__ Wih_d, const float* __restrict__ bih_d)
{
    __shared__ float Xs[64][68];   // [k][pos]
    __shared__ float Ws[64][68];   // [k][gate]

    const int tileP = blockIdx.x;
    const bool enc = (tileP < (ENC_LEN / 64));
    const float* __restrict__ Wih = enc ? Wih_e : Wih_d;
    const float* __restrict__ bih = enc ? bih_e : bih_d;
    float* __restrict__ gout = enc ? g_gi_enc : g_gi_dec;
    const int p0 = (enc ? tileP : (tileP - ENC_LEN / 64)) * 64;
    const int g0 = blockIdx.y * 64;
    const int tid = threadIdx.x;
    const int tstride = enc ? 1 : 8;

    const int tx = tid & 15;
    const int ty = tid >> 4;
    float acc[4][4] = {};

    for (int kc = 0; kc < 2; ++kc) {
        #pragma unroll
        for (int i = tid; i < 64 * 64; i += 256) {
            int pos = i >> 6, k = i & 63;
            int p = p0 + pos;
            int b = p & 127, t = (p >> 7) * tstride;
            Xs[k][pos] = x[((size_t)b * T_IN_ + t) * D_ + kc * 64 + k];
        }
        #pragma unroll
        for (int i = tid; i < 64 * 64; i += 256) {
            int g = i >> 6, k = i & 63;
            Ws[k][g] = Wih[(size_t)(g0 + g) * D_ + kc * 64 + k];
        }
        __syncthreads();

        #pragma unroll 16
        for (int k = 0; k < 64; ++k) {
            float4 a = *(const float4*)&Xs[k][ty * 4];
            float4 b = *(const float4*)&Ws[k][tx * 4];
            float av[4] = {a.x, a.y, a.z, a.w};
            float bv[4] = {b.x, b.y, b.z, b.w};
            #pragma unroll
            for (int i = 0; i < 4; ++i)
                #pragma unroll
                for (int j = 0; j < 4; ++j)
                    acc[i][j] = fmaf(av[i], bv[j], acc[i][j]);
        }
        __syncthreads();
    }

    float bz[4];
    #pragma unroll
    for (int j = 0; j < 4; ++j) bz[j] = bih[g0 + tx * 4 + j];

    #pragma unroll
    for (int i = 0; i < 4; ++i) {
        int p = p0 + ty * 4 + i;
        float4 o;
        o.x = acc[i][0] + bz[0];
        o.y = acc[i][1] + bz[1];
        o.z = acc[i][2] + bz[2];
        o.w = acc[i][3] + bz[3];
        *(float4*)&gout[(size_t)p * G3_ + g0 + tx * 4] = o;
    }
}

// ============================================================
// Phase 2: segmented GRU scan — register-resident weights,
// packed f32x2 FMA, st.async + mbarrier cluster exchange.
// 384 threads: 2 threads per gh-row (row = tid>>1, half = tid&1).
// ============================================================
__global__ __launch_bounds__(384, 1) __cluster_dims__(4, 1, 1)
void gru_scan(const float* __restrict__ Whh_e, const float* __restrict__ bhh_e,
              const float* __restrict__ Whh_d, const float* __restrict__ bhh_d,
              float* __restrict__ out)
{
    __shared__ __align__(16) float hbuf[2][256];
    __shared__ float sGH[192];
    __shared__ float sGI[192];
    __shared__ __align__(8) unsigned long long mbars[2];

    const int tid = threadIdx.x;
    uint32_t rank;
    asm("mov.u32 %0, %%cluster_ctarank;" : "=r"(rank));

    const int seg  = blockIdx.x >> 2;
    const bool enc = seg < NSEG_ENC;
    const int lseg = enc ? seg : seg - NSEG_ENC;
    const float* __restrict__ Whh = enc ? Whh_e : Whh_d;
    const float* __restrict__ bhh = enc ? bhh_e : bhh_d;
    const float* __restrict__ gi  = enc ? g_gi_enc : g_gi_dec;

    const int out_begin = lseg * CHUNK;
    const int out_end   = out_begin + CHUNK;
    int start = out_begin - WARMUP;
    if (start < 0) start = 0;

    // ---- thread mapping ----
    const int gr   = tid >> 1;          // gh row 0..191
    const int half = tid & 1;           // which 128-col half
    const int gate = gr >> 6;
    const int jl   = gr & 63;
    const int Rg   = gate * 256 + (int)rank * 64 + jl;   // global Whh row

    // ---- load 128 weights into registers (as 64 packed f32x2) ----
    unsigned long long w[64];
    {
        const ulonglong2* wsrc =
            (const ulonglong2*)(Whh + (size_t)Rg * H_ + half * 128);
        #pragma unroll
        for (int i = 0; i < 32; ++i) {
            ulonglong2 t = wsrc[i];
            w[2 * i]     = t.x;
            w[2 * i + 1] = t.y;
        }
    }
    const float bias = (half == 0) ? bhh[Rg] : 0.0f;

    // ---- init shared state ----
    if (tid < 256) { hbuf[0][tid] = 0.0f; hbuf[1][tid] = 0.0f; }
    uint32_t mb0 = smem_u32(&mbars[0]);
    uint32_t mb1 = smem_u32(&mbars[1]);
    if (tid == 0) { mbar_init(mb0, 1); mbar_init(mb1, 1); }
    __syncthreads();
    // pre-arm mb[1]: first stores (step `start`) complete on it
    if (tid == 0) mbar_arrive_expect(mb1, 1024);
    cl_sync();   // everyone armed + zeroed before any remote traffic

    // peer addresses
    uint32_t my_hb = smem_u32(&hbuf[0][0]);
    uint32_t peer_hb[4], peer_mb[4];
    #pragma unroll
    for (int r = 0; r < 4; ++r) {
        peer_hb[r] = mapa_u32(my_hb, r);
        peer_mb[r] = mapa_u32(mb0, r);
    }

    const size_t gi_off = (size_t)gate * 256 + rank * 64 + jl;

    // gi prefetch (software pipelined one step ahead)
    float gi_next = 0.0f;
    if (half == 0) gi_next = __ldg(&gi[(size_t)start * G3_ + gi_off]);

    uint32_t mb_phase[2] = {0u, 0u};

    for (int p = start; p < out_end; ++p) {
        const int s  = p - start;
        const int ph = s & 1;

        // re-arm mb[ph] for its next completion (end of step p+1).
        // Must precede this step's stores (peers need them to reach p+1).
        if (tid == 0) mbar_arrive_expect(ph ? mb1 : mb0, 1024);

        float giv = gi_next;
        if (half == 0 && p + 1 < out_end)
            gi_next = __ldg(&gi[(size_t)(p + 1) * G3_ + gi_off]);

        // ---- matvec: gh[gr] = Whh[Rg,:] . h ----
        const ulonglong2* h2 =
            (const ulonglong2*)(&hbuf[ph][0] + (half << 7));
        unsigned long long acc = 0ull;   // packed (0.0f, 0.0f)
        #pragma unroll
        for (int i = 0; i < 32; ++i) {
            ulonglong2 hv = h2[i];
            acc = ffma2(w[2 * i],     hv.x, acc);
            acc = ffma2(w[2 * i + 1], hv.y, acc);
        }
        float lo = __uint_as_float((unsigned)(acc & 0xffffffffull));
        float hi = __uint_as_float((unsigned)(acc >> 32));
        float sum = lo + hi;
        sum += __shfl_xor_sync(0xffffffffu, sum, 1);

        if (half == 0) {
            sGH[gr] = sum + bias;
            sGI[gr] = giv;
        }
        __syncthreads();

        if (tid < 64) {
            float r_ = sig_(sGI[tid]       + sGH[tid]);
            float z_ = sig_(sGI[64 + tid]  + sGH[64 + tid]);
            float n_ = th_ (sGI[128 + tid] + r_ * sGH[128 + tid]);
            float hold = hbuf[ph][(int)rank * 64 + tid];
            float hn = (1.0f - z_) * n_ + z_ * hold;

            // broadcast h' into buf[ph^1] of all 4 CTAs, completing tx on mb[ph^1]
            uint32_t boff = (uint32_t)(((ph ^ 1) << 8) + ((int)rank * 64 + tid)) * 4u;
            uint32_t moff = (uint32_t)(ph ^ 1) * 8u;
            #pragma unroll
            for (int r = 0; r < 4; ++r)
                st_async_f32(peer_hb[r] + boff, hn, peer_mb[r] + moff);

            // outputs
            if (p >= out_begin) {
                if (enc) {
                    if ((p & 127) == 127) {
                        int t_out = p >> 7;
                        out[(size_t)t_out * H_ + rank * 64 + tid] = hn;
                    }
                } else {
                    int b = p & 127, t = p >> 7;
                    out[(size_t)(T_IN_ * H_) +
                        ((size_t)b * T_OUT_ + t) * H_ + rank * 64 + tid] = hn;
                }
            }
        }

        // wait for all 4 CTAs' h' (1024 bytes) on mb[ph^1]
        uint32_t wb = ph ^ 1;
        mbar_wait_parity(wb ? mb1 : mb0, mb_phase[wb] & 1u);
        mb_phase[wb]++;
    }

    cl_sync();   // keep cluster alive until all async traffic drained
}

// ============================================================
// launch
// ============================================================
extern "C" void kernel_launch(void* const* d_in, const int* in_sizes, int n_in,
                              void* d_out, int out_size)
{
    const float* x     = (const float*)d_in[0];
    const float* Wih_e = (const float*)d_in[1];
    const float* Whh_e = (const float*)d_in[2];
    const float* bih_e = (const float*)d_in[3];
    const float* bhh_e = (const float*)d_in[4];
    const float* Wih_d = (const float*)d_in[5];
    const float* Whh_d = (const float*)d_in[6];
    const float* bih_d = (const float*)d_in[7];
    const float* bhh_d = (const float*)d_in[8];
    float* out = (float*)d_out;

    dim3 ggrid(ENC_LEN / 64 + DEC_LEN / 64, G3_ / 64);  // (540, 12)
    gi_gemm<<<ggrid, 256>>>(x, Wih_e, bih_e, Wih_d, bih_d);

    gru_scan<<<(NSEG_ENC + NSEG_DEC) * 4, 384>>>(
        Whh_e, bhh_e, Whh_d, bhh_d, out);
}

// round 4
// speedup vs baseline: 1.7184x; 1.0793x over previous
#include <cuda_runtime.h>
#include <cstdint>

// ---------------- problem constants ----------------
#define B_      128
#define T_IN_   240
#define T_OUT_  30
#define D_      128
#define H_      256
#define G3_     768

#define ENC_LEN 30720   // T_IN * B
#define DEC_LEN 3840    // T_OUT * B

// segmentation: 2 chains per 4-CTA cluster
#define CHAINS   2
#define CHUNK    480     // 64 enc segs * 480 = 30720 ; 8 dec segs * 480 = 3840
#define WARMUP   192
#define STEPS    (CHUNK + WARMUP)   // 672
#define NCL_ENC  32
#define NCL_DEC  4

// ---------------- device scratch ----------------
__device__ float g_gi_enc[(size_t)ENC_LEN * G3_];   // ~94 MB
__device__ float g_gi_dec[(size_t)DEC_LEN * G3_];   // ~12 MB

// ---------------- helpers ----------------
__device__ __forceinline__ uint32_t smem_u32(const void* p) {
    return (uint32_t)__cvta_generic_to_shared(p);
}
__device__ __forceinline__ uint32_t mapa_u32(uint32_t addr, uint32_t rank) {
    uint32_t d;
    asm("mapa.shared::cluster.u32 %0, %1, %2;" : "=r"(d) : "r"(addr), "r"(rank));
    return d;
}
__device__ __forceinline__ void cl_sync() {
    asm volatile("barrier.cluster.arrive.aligned;" ::: "memory");
    asm volatile("barrier.cluster.wait.aligned;"   ::: "memory");
}
__device__ __forceinline__ void mbar_init(uint32_t mbar, uint32_t count) {
    asm volatile("mbarrier.init.shared.b64 [%0], %1;" :: "r"(mbar), "r"(count) : "memory");
}
__device__ __forceinline__ void mbar_arrive_expect(uint32_t mbar, uint32_t bytes) {
    asm volatile("mbarrier.arrive.expect_tx.shared::cta.b64 _, [%0], %1;"
                 :: "r"(mbar), "r"(bytes) : "memory");
}
__device__ __forceinline__ void mbar_wait_parity(uint32_t mbar, uint32_t parity) {
    uint32_t done;
    asm volatile(
        "{\n\t.reg .pred p;\n\t"
        "mbarrier.try_wait.parity.acquire.cta.shared::cta.b64 p, [%1], %2;\n\t"
        "selp.b32 %0, 1, 0, p;\n\t}"
        : "=r"(done) : "r"(mbar), "r"(parity) : "memory");
    if (!done) {
        asm volatile(
            "{\n\t.reg .pred P1;\n\t"
            "WAIT_LOOP_%=:\n\t"
            "mbarrier.try_wait.parity.acquire.cta.shared::cta.b64 P1, [%0], %1, 0x989680;\n\t"
            "@P1 bra.uni WAIT_DONE_%=;\n\t"
            "bra.uni WAIT_LOOP_%=;\n\t"
            "WAIT_DONE_%=:\n\t}"
            :: "r"(mbar), "r"(parity) : "memory");
    }
}
__device__ __forceinline__ void st_async_f32(uint32_t addr, float v, uint32_t mbar) {
    asm volatile(
        "st.async.weak.shared::cluster.mbarrier::complete_tx::bytes.f32 [%0], %1, [%2];"
        :: "r"(addr), "f"(v), "r"(mbar) : "memory");
}
__device__ __forceinline__ unsigned long long ffma2(unsigned long long a,
                                                    unsigned long long b,
                                                    unsigned long long c) {
    unsigned long long r;
    asm("fma.rn.f32x2 %0, %1, %2, %3;" : "=l"(r) : "l"(a), "l"(b), "l"(c));
    return r;
}
__device__ __forceinline__ float f2lo(unsigned long long v) {
    return __uint_as_float((unsigned)(v & 0xffffffffull));
}
__device__ __forceinline__ float f2hi(unsigned long long v) {
    return __uint_as_float((unsigned)(v >> 32));
}
__device__ __forceinline__ float sig_(float x) { return 1.0f / (1.0f + __expf(-x)); }
__device__ __forceinline__ float th_(float x)  { return 2.0f / (1.0f + __expf(-2.0f * x)) - 1.0f; }

// ============================================================
// Phase 1: GI = X @ Wih^T + bih  (unchanged — verified)
// ============================================================
__global__ __launch_bounds__(256)
void gi_gemm(const float* __restrict__ x,
             const float* __restrict__ Wih_e, const float* __restrict__ bih_e,
             const float* __restrict__ Wih_d, const float* __restrict__ bih_d)
{
    __shared__ float Xs[64][68];   // [k][pos]
    __shared__ float Ws[64][68];   // [k][gate]

    const int tileP = blockIdx.x;
    const bool enc = (tileP < (ENC_LEN / 64));
    const float* __restrict__ Wih = enc ? Wih_e : Wih_d;
    const float* __restrict__ bih = enc ? bih_e : bih_d;
    float* __restrict__ gout = enc ? g_gi_enc : g_gi_dec;
    const int p0 = (enc ? tileP : (tileP - ENC_LEN / 64)) * 64;
    const int g0 = blockIdx.y * 64;
    const int tid = threadIdx.x;
    const int tstride = enc ? 1 : 8;

    const int tx = tid & 15;
    const int ty = tid >> 4;
    float acc[4][4] = {};

    for (int kc = 0; kc < 2; ++kc) {
        #pragma unroll
        for (int i = tid; i < 64 * 64; i += 256) {
            int pos = i >> 6, k = i & 63;
            int p = p0 + pos;
            int b = p & 127, t = (p >> 7) * tstride;
            Xs[k][pos] = x[((size_t)b * T_IN_ + t) * D_ + kc * 64 + k];
        }
        #pragma unroll
        for (int i = tid; i < 64 * 64; i += 256) {
            int g = i >> 6, k = i & 63;
            Ws[k][g] = Wih[(size_t)(g0 + g) * D_ + kc * 64 + k];
        }
        __syncthreads();

        #pragma unroll 16
        for (int k = 0; k < 64; ++k) {
            float4 a = *(const float4*)&Xs[k][ty * 4];
            float4 b = *(const float4*)&Ws[k][tx * 4];
            float av[4] = {a.x, a.y, a.z, a.w};
            float bv[4] = {b.x, b.y, b.z, b.w};
            #pragma unroll
            for (int i = 0; i < 4; ++i)
                #pragma unroll
                for (int j = 0; j < 4; ++j)
                    acc[i][j] = fmaf(av[i], bv[j], acc[i][j]);
        }
        __syncthreads();
    }

    float bz[4];
    #pragma unroll
    for (int j = 0; j < 4; ++j) bz[j] = bih[g0 + tx * 4 + j];

    #pragma unroll
    for (int i = 0; i < 4; ++i) {
        int p = p0 + ty * 4 + i;
        float4 o;
        o.x = acc[i][0] + bz[0];
        o.y = acc[i][1] + bz[1];
        o.z = acc[i][2] + bz[2];
        o.w = acc[i][3] + bz[3];
        *(float4*)&gout[(size_t)p * G3_ + g0 + tx * 4] = o;
    }
}

// ============================================================
// Phase 2: segmented GRU scan — 2 independent chains per cluster
// (shared register-resident weights), packed f32x2 FMA (4 accs),
// st.async + mbarrier exchange.
// 384 threads: gh row = tid>>1 (0..191), half = tid&1.
// ============================================================
__global__ __launch_bounds__(384, 1) __cluster_dims__(4, 1, 1)
void gru_scan(const float* __restrict__ Whh_e, const float* __restrict__ bhh_e,
              const float* __restrict__ Whh_d, const float* __restrict__ bhh_d,
              float* __restrict__ out)
{
    __shared__ __align__(16) float hbuf[2][CHAINS][256];  // [parity][chain][H]
    __shared__ float sGH[CHAINS][192];
    __shared__ float sGI[CHAINS][192];
    __shared__ __align__(8) unsigned long long mbars[2];

    const int tid = threadIdx.x;
    uint32_t rank;
    asm("mov.u32 %0, %%cluster_ctarank;" : "=r"(rank));

    const int cl   = blockIdx.x >> 2;
    const bool enc = cl < NCL_ENC;
    const int lcl  = enc ? cl : cl - NCL_ENC;
    const float* __restrict__ Whh = enc ? Whh_e : Whh_d;
    const float* __restrict__ bhh = enc ? bhh_e : bhh_d;
    const float* __restrict__ gi  = enc ? g_gi_enc : g_gi_dec;

    int base[CHAINS];
    #pragma unroll
    for (int c = 0; c < CHAINS; ++c)
        base[c] = (lcl * CHAINS + c) * CHUNK;

    // ---- thread mapping ----
    const int gr   = tid >> 1;          // gh row 0..191
    const int half = tid & 1;           // 128-col half
    const int gate = gr >> 6;
    const int jl   = gr & 63;
    const int Rg   = gate * 256 + (int)rank * 64 + jl;

    // ---- 128 weights in registers (64 packed f32x2) ----
    unsigned long long w[64];
    {
        const ulonglong2* wsrc =
            (const ulonglong2*)(Whh + (size_t)Rg * H_ + half * 128);
        #pragma unroll
        for (int i = 0; i < 32; ++i) {
            ulonglong2 t = wsrc[i];
            w[2 * i]     = t.x;
            w[2 * i + 1] = t.y;
        }
    }
    const float bias = (half == 0) ? bhh[Rg] : 0.0f;

    // ---- init shared state ----
    for (int i = tid; i < 2 * CHAINS * 256; i += 384)
        ((float*)hbuf)[i] = 0.0f;
    uint32_t mb0 = smem_u32(&mbars[0]);
    uint32_t mb1 = smem_u32(&mbars[1]);
    if (tid == 0) { mbar_init(mb0, 1); mbar_init(mb1, 1); }
    __syncthreads();
    if (tid == 0) mbar_arrive_expect(mb1, 1024 * CHAINS);  // s=0 stores land here
    cl_sync();

    // peer addresses
    uint32_t my_hb = smem_u32(&hbuf[0][0][0]);
    uint32_t peer_hb[4], peer_mb[4];
    #pragma unroll
    for (int r = 0; r < 4; ++r) {
        peer_hb[r] = mapa_u32(my_hb, r);
        peer_mb[r] = mapa_u32(mb0, r);
    }

    const size_t gi_off = (size_t)gate * 256 + rank * 64 + jl;

    // per-chain gi prefetch (one step ahead)
    float gin[CHAINS];
    #pragma unroll
    for (int c = 0; c < CHAINS; ++c) {
        int p0 = base[c] - WARMUP; if (p0 < 0) p0 = 0;
        gin[c] = (half == 0) ? __ldg(&gi[(size_t)p0 * G3_ + gi_off]) : 0.0f;
    }

    uint32_t mb_phase[2] = {0u, 0u};

    for (int s = 0; s < STEPS; ++s) {
        const int ph = s & 1;

        // re-arm mb[ph] for step s+1's stores (syncthreads below orders
        // this before any gate-thread store of this step)
        if (tid == 0) mbar_arrive_expect(ph ? mb1 : mb0, 1024 * CHAINS);

        // ---- matvec for both chains ----
        #pragma unroll
        for (int c = 0; c < CHAINS; ++c) {
            float giv = gin[c];
            if (half == 0 && s + 1 < STEPS) {
                int pn = base[c] + s + 1 - WARMUP; if (pn < 0) pn = 0;
                gin[c] = __ldg(&gi[(size_t)pn * G3_ + gi_off]);
            }

            const ulonglong2* h2 =
                (const ulonglong2*)(&hbuf[ph][c][0] + (half << 7));
            unsigned long long a0 = 0ull, a1 = 0ull, a2 = 0ull, a3 = 0ull;
            #pragma unroll
            for (int i = 0; i < 16; ++i) {
                ulonglong2 hva = h2[2 * i];
                ulonglong2 hvb = h2[2 * i + 1];
                a0 = ffma2(w[4 * i],     hva.x, a0);
                a1 = ffma2(w[4 * i + 1], hva.y, a1);
                a2 = ffma2(w[4 * i + 2], hvb.x, a2);
                a3 = ffma2(w[4 * i + 3], hvb.y, a3);
            }
            float sum = (f2lo(a0) + f2hi(a0)) + (f2lo(a1) + f2hi(a1))
                      + (f2lo(a2) + f2hi(a2)) + (f2lo(a3) + f2hi(a3));
            sum += __shfl_xor_sync(0xffffffffu, sum, 1);

            if (half == 0) {
                sGH[c][gr] = sum + bias;
                sGI[c][gr] = giv;
            }
        }
        __syncthreads();

        // ---- gates: 128 threads = 2 chains x 64 coords ----
        if (tid < 64 * CHAINS) {
            const int c = tid >> 6;
            const int j = tid & 63;
            const int p = base[c] + s - WARMUP;

            float r_ = sig_(sGI[c][j]       + sGH[c][j]);
            float z_ = sig_(sGI[c][64 + j]  + sGH[c][64 + j]);
            float n_ = th_ (sGI[c][128 + j] + r_ * sGH[c][128 + j]);
            float hold = hbuf[ph][c][(int)rank * 64 + j];
            float hn = (1.0f - z_) * n_ + z_ * hold;
            if (p < 0) hn = 0.0f;   // pre-sequence region of first segment

            uint32_t boff = (uint32_t)((((ph ^ 1) * CHAINS + c) << 8)
                                       + (int)rank * 64 + j) * 4u;
            uint32_t moff = (uint32_t)(ph ^ 1) * 8u;
            #pragma unroll
            for (int r = 0; r < 4; ++r)
                st_async_f32(peer_hb[r] + boff, hn, peer_mb[r] + moff);

            if (s >= WARMUP) {
                if (enc) {
                    if ((p & 127) == 127) {
                        int t_out = p >> 7;
                        out[(size_t)t_out * H_ + rank * 64 + j] = hn;
                    }
                } else {
                    int b = p & 127, t = p >> 7;
                    out[(size_t)(T_IN_ * H_) +
                        ((size_t)b * T_OUT_ + t) * H_ + rank * 64 + j] = hn;
                }
            }
        }

        // wait for both chains' h' (2048 bytes from 4 CTAs) on mb[ph^1]
        const uint32_t wb = ph ^ 1;
        mbar_wait_parity(wb ? mb1 : mb0, mb_phase[wb] & 1u);
        mb_phase[wb]++;
    }

    cl_sync();   // drain async traffic before cluster teardown
}

// ============================================================
// launch
// ============================================================
extern "C" void kernel_launch(void* const* d_in, const int* in_sizes, int n_in,
                              void* d_out, int out_size)
{
    const float* x     = (const float*)d_in[0];
    const float* Wih_e = (const float*)d_in[1];
    const float* Whh_e = (const float*)d_in[2];
    const float* bih_e = (const float*)d_in[3];
    const float* bhh_e = (const float*)d_in[4];
    const float* Wih_d = (const float*)d_in[5];
    const float* Whh_d = (const float*)d_in[6];
    const float* bih_d = (const float*)d_in[7];
    const float* bhh_d = (const float*)d_in[8];
    float* out = (float*)d_out;

    dim3 ggrid(ENC_LEN / 64 + DEC_LEN / 64, G3_ / 64);  // (540, 12)
    gi_gemm<<<ggrid, 256>>>(x, Wih_e, bih_e, Wih_d, bih_d);

    gru_scan<<<(NCL_ENC + NCL_DEC) * 4, 384>>>(
        Whh_e, bhh_e, Whh_d, bhh_d, out);
}

// round 5
// speedup vs baseline: 1.8030x; 1.0492x over previous
#include <cuda_runtime.h>
#include <cstdint>

// ---------------- problem constants ----------------
#define B_      128
#define T_IN_   240
#define T_OUT_  30
#define D_      128
#define H_      256
#define G3_     768

#define ENC_LEN 30720   // T_IN * B
#define DEC_LEN 3840    // T_OUT * B

// segmentation: 2 chains per 4-CTA cluster
#define CHAINS   2
#define CHUNK    480     // 64 enc segs * 480 = 30720 ; 8 dec segs * 480 = 3840
#define WARMUP   192
#define STEPS    (CHUNK + WARMUP)   // 672
#define NCL_ENC  32
#define NCL_DEC  4

// ---------------- device scratch ----------------
__device__ float g_gi_enc[(size_t)ENC_LEN * G3_];   // ~94 MB
__device__ float g_gi_dec[(size_t)DEC_LEN * G3_];   // ~12 MB

// ---------------- helpers ----------------
__device__ __forceinline__ uint32_t smem_u32(const void* p) {
    return (uint32_t)__cvta_generic_to_shared(p);
}
__device__ __forceinline__ uint32_t mapa_u32(uint32_t addr, uint32_t rank) {
    uint32_t d;
    asm("mapa.shared::cluster.u32 %0, %1, %2;" : "=r"(d) : "r"(addr), "r"(rank));
    return d;
}
__device__ __forceinline__ void cl_sync() {
    asm volatile("barrier.cluster.arrive.aligned;" ::: "memory");
    asm volatile("barrier.cluster.wait.aligned;"   ::: "memory");
}
__device__ __forceinline__ void mbar_init(uint32_t mbar, uint32_t count) {
    asm volatile("mbarrier.init.shared.b64 [%0], %1;" :: "r"(mbar), "r"(count) : "memory");
}
__device__ __forceinline__ void mbar_arrive_expect(uint32_t mbar, uint32_t bytes) {
    asm volatile("mbarrier.arrive.expect_tx.shared::cta.b64 _, [%0], %1;"
                 :: "r"(mbar), "r"(bytes) : "memory");
}
__device__ __forceinline__ void mbar_wait_parity(uint32_t mbar, uint32_t parity) {
    uint32_t done;
    asm volatile(
        "{\n\t.reg .pred p;\n\t"
        "mbarrier.try_wait.parity.acquire.cta.shared::cta.b64 p, [%1], %2;\n\t"
        "selp.b32 %0, 1, 0, p;\n\t}"
        : "=r"(done) : "r"(mbar), "r"(parity) : "memory");
    if (!done) {
        asm volatile(
            "{\n\t.reg .pred P1;\n\t"
            "WAIT_LOOP_%=:\n\t"
            "mbarrier.try_wait.parity.acquire.cta.shared::cta.b64 P1, [%0], %1, 0x989680;\n\t"
            "@P1 bra.uni WAIT_DONE_%=;\n\t"
            "bra.uni WAIT_LOOP_%=;\n\t"
            "WAIT_DONE_%=:\n\t}"
            :: "r"(mbar), "r"(parity) : "memory");
    }
}
__device__ __forceinline__ void st_async_f32(uint32_t addr, float v, uint32_t mbar) {
    asm volatile(
        "st.async.weak.shared::cluster.mbarrier::complete_tx::bytes.f32 [%0], %1, [%2];"
        :: "r"(addr), "f"(v), "r"(mbar) : "memory");
}
__device__ __forceinline__ unsigned long long ffma2(unsigned long long a,
                                                    unsigned long long b,
                                                    unsigned long long c) {
    unsigned long long r;
    asm("fma.rn.f32x2 %0, %1, %2, %3;" : "=l"(r) : "l"(a), "l"(b), "l"(c));
    return r;
}
__device__ __forceinline__ float f2lo(unsigned long long v) {
    return __uint_as_float((unsigned)(v & 0xffffffffull));
}
__device__ __forceinline__ float f2hi(unsigned long long v) {
    return __uint_as_float((unsigned)(v >> 32));
}
__device__ __forceinline__ float sig_(float x) { return 1.0f / (1.0f + __expf(-x)); }
__device__ __forceinline__ float th_(float x)  { return 2.0f / (1.0f + __expf(-2.0f * x)) - 1.0f; }

// ============================================================
// Phase 1: GI = X @ Wih^T + bih  (unchanged — verified)
// ============================================================
__global__ __launch_bounds__(256)
void gi_gemm(const float* __restrict__ x,
             const float* __restrict__ Wih_e, const float* __restrict__ bih_e,
             const float* __restrict__ Wih_d, const float* __restrict__ bih_d)
{
    __shared__ float Xs[64][68];   // [k][pos]
    __shared__ float Ws[64][68];   // [k][gate]

    const int tileP = blockIdx.x;
    const bool enc = (tileP < (ENC_LEN / 64));
    const float* __restrict__ Wih = enc ? Wih_e : Wih_d;
    const float* __restrict__ bih = enc ? bih_e : bih_d;
    float* __restrict__ gout = enc ? g_gi_enc : g_gi_dec;
    const int p0 = (enc ? tileP : (tileP - ENC_LEN / 64)) * 64;
    const int g0 = blockIdx.y * 64;
    const int tid = threadIdx.x;
    const int tstride = enc ? 1 : 8;

    const int tx = tid & 15;
    const int ty = tid >> 4;
    float acc[4][4] = {};

    for (int kc = 0; kc < 2; ++kc) {
        #pragma unroll
        for (int i = tid; i < 64 * 64; i += 256) {
            int pos = i >> 6, k = i & 63;
            int p = p0 + pos;
            int b = p & 127, t = (p >> 7) * tstride;
            Xs[k][pos] = x[((size_t)b * T_IN_ + t) * D_ + kc * 64 + k];
        }
        #pragma unroll
        for (int i = tid; i < 64 * 64; i += 256) {
            int g = i >> 6, k = i & 63;
            Ws[k][g] = Wih[(size_t)(g0 + g) * D_ + kc * 64 + k];
        }
        __syncthreads();

        #pragma unroll 16
        for (int k = 0; k < 64; ++k) {
            float4 a = *(const float4*)&Xs[k][ty * 4];
            float4 b = *(const float4*)&Ws[k][tx * 4];
            float av[4] = {a.x, a.y, a.z, a.w};
            float bv[4] = {b.x, b.y, b.z, b.w};
            #pragma unroll
            for (int i = 0; i < 4; ++i)
                #pragma unroll
                for (int j = 0; j < 4; ++j)
                    acc[i][j] = fmaf(av[i], bv[j], acc[i][j]);
        }
        __syncthreads();
    }

    float bz[4];
    #pragma unroll
    for (int j = 0; j < 4; ++j) bz[j] = bih[g0 + tx * 4 + j];

    #pragma unroll
    for (int i = 0; i < 4; ++i) {
        int p = p0 + ty * 4 + i;
        float4 o;
        o.x = acc[i][0] + bz[0];
        o.y = acc[i][1] + bz[1];
        o.z = acc[i][2] + bz[2];
        o.w = acc[i][3] + bz[3];
        *(float4*)&gout[(size_t)p * G3_ + g0 + tx * 4] = o;
    }
}

// ============================================================
// Phase 2: segmented GRU scan.
// - warps 0-5  : rows 0..191, half 0 (h[0..127])
// - warps 6-11 : rows 0..191, half 1 (h[128..255])
//   => every LDS of h is all-lanes-same-address (pure broadcast).
// - halves combined via SMEM partials (no shuffles).
// - 2 chains per cluster, pipelined half-steps: each chain's
//   DSMEM exchange latency hides under the other chain's matvec.
// ============================================================
__global__ __launch_bounds__(384, 1) __cluster_dims__(4, 1, 1)
void gru_scan(const float* __restrict__ Whh_e, const float* __restrict__ bhh_e,
              const float* __restrict__ Whh_d, const float* __restrict__ bhh_d,
              float* __restrict__ out)
{
    __shared__ __align__(16) float hbuf[2][CHAINS][256];   // [parity][chain][H]
    __shared__ float sGHp[CHAINS][2][192];                 // [chain][half][row]
    __shared__ float sGI[CHAINS][192];
    __shared__ float sBH[192];
    __shared__ __align__(8) unsigned long long mbars[CHAINS][2];

    const int tid  = threadIdx.x;
    const int warp = tid >> 5;
    const int lane = tid & 31;
    uint32_t rank;
    asm("mov.u32 %0, %%cluster_ctarank;" : "=r"(rank));

    const int cl   = blockIdx.x >> 2;
    const bool enc = cl < NCL_ENC;
    const int lcl  = enc ? cl : cl - NCL_ENC;
    const float* __restrict__ Whh = enc ? Whh_e : Whh_d;
    const float* __restrict__ bhh = enc ? bhh_e : bhh_d;
    const float* __restrict__ gi  = enc ? g_gi_enc : g_gi_dec;

    int base[CHAINS];
    #pragma unroll
    for (int c = 0; c < CHAINS; ++c)
        base[c] = (lcl * CHAINS + c) * CHUNK;

    // ---- thread mapping: whole warp = one half ----
    const int half = (warp >= 6) ? 1 : 0;
    const int row  = ((half ? warp - 6 : warp) << 5) + lane;   // 0..191
    const int gate = row >> 6;
    const int jl   = row & 63;
    const int Rg   = gate * 256 + (int)rank * 64 + jl;

    // ---- 128 weights in registers (64 packed f32x2) ----
    unsigned long long w[64];
    {
        const ulonglong2* wsrc =
            (const ulonglong2*)(Whh + (size_t)Rg * H_ + half * 128);
        #pragma unroll
        for (int i = 0; i < 32; ++i) {
            ulonglong2 t = wsrc[i];
            w[2 * i]     = t.x;
            w[2 * i + 1] = t.y;
        }
    }

    // ---- init shared state ----
    for (int i = tid; i < 2 * CHAINS * 256; i += 384)
        ((float*)hbuf)[i] = 0.0f;
    if (tid < 192) {
        int g = tid >> 6, j = tid & 63;
        sBH[tid] = bhh[g * 256 + (int)rank * 64 + j];
    }
    uint32_t mb_base = smem_u32(&mbars[0][0]);
    if (tid == 0) {
        #pragma unroll
        for (int i = 0; i < 2 * CHAINS; ++i) mbar_init(mb_base + i * 8, 1);
    }
    __syncthreads();
    cl_sync();   // barriers + zeroed buffers visible cluster-wide

    // peer addresses
    uint32_t my_hb = smem_u32(&hbuf[0][0][0]);
    uint32_t peer_hb[4], peer_mb[4];
    #pragma unroll
    for (int r = 0; r < 4; ++r) {
        peer_hb[r] = mapa_u32(my_hb, r);
        peer_mb[r] = mapa_u32(mb_base, r);
    }

    const size_t gi_off = (size_t)gate * 256 + rank * 64 + jl;

    // per-chain gi prefetch (half-0 threads only)
    float gin[CHAINS];
    #pragma unroll
    for (int c = 0; c < CHAINS; ++c) {
        int p0 = base[c] - WARMUP; if (p0 < 0) p0 = 0;
        gin[c] = (half == 0) ? __ldg(&gi[(size_t)p0 * G3_ + gi_off]) : 0.0f;
    }

    uint32_t mph[CHAINS][2] = {{0u, 0u}, {0u, 0u}};

    for (int s = 0; s < STEPS; ++s) {
        const int ph = s & 1;

        #pragma unroll
        for (int c = 0; c < CHAINS; ++c) {
            // arm mbar[c][ph^1] for h_c(s+1) arrivals.
            // Safe: our own wait on this barrier's previous phase passed at
            // step s-1; syncthreads below orders it before our gate stores.
            if (tid == 320)
                mbar_arrive_expect(mb_base + (c * 2 + (ph ^ 1)) * 8, 1024);

            // wait for h_c(s) (arrived during the other chain's half-step)
            if (s > 0) {
                mbar_wait_parity(mb_base + (c * 2 + ph) * 8, mph[c][ph] & 1u);
                mph[c][ph]++;
            }

            // ---- matvec: all-lanes-same-address broadcast LDS ----
            float giv = gin[c];
            if (half == 0 && s + 1 < STEPS) {
                int pn = base[c] + s + 1 - WARMUP; if (pn < 0) pn = 0;
                gin[c] = __ldg(&gi[(size_t)pn * G3_ + gi_off]);
            }

            const ulonglong2* h2 =
                (const ulonglong2*)(&hbuf[ph][c][0] + (half << 7));
            unsigned long long a0 = 0ull, a1 = 0ull, a2 = 0ull, a3 = 0ull;
            #pragma unroll
            for (int i = 0; i < 16; ++i) {
                ulonglong2 hva = h2[2 * i];
                ulonglong2 hvb = h2[2 * i + 1];
                a0 = ffma2(w[4 * i],     hva.x, a0);
                a1 = ffma2(w[4 * i + 1], hva.y, a1);
                a2 = ffma2(w[4 * i + 2], hvb.x, a2);
                a3 = ffma2(w[4 * i + 3], hvb.y, a3);
            }
            float sum = (f2lo(a0) + f2hi(a0)) + (f2lo(a1) + f2hi(a1))
                      + (f2lo(a2) + f2hi(a2)) + (f2lo(a3) + f2hi(a3));
            sGHp[c][half][row] = sum;
            if (half == 0) sGI[c][row] = giv;
            __syncthreads();

            // ---- gates (64 threads), st.async; NO wait here ----
            if (tid < 64) {
                const int j = tid;
                const int p = base[c] + s - WARMUP;

                float ghr = sGHp[c][0][j]       + sGHp[c][1][j]       + sBH[j];
                float ghz = sGHp[c][0][64 + j]  + sGHp[c][1][64 + j]  + sBH[64 + j];
                float ghn = sGHp[c][0][128 + j] + sGHp[c][1][128 + j] + sBH[128 + j];
                float r_ = sig_(sGI[c][j]       + ghr);
                float z_ = sig_(sGI[c][64 + j]  + ghz);
                float n_ = th_ (sGI[c][128 + j] + r_ * ghn);
                float hold = hbuf[ph][c][(int)rank * 64 + j];
                float hn = (1.0f - z_) * n_ + z_ * hold;
                if (p < 0) hn = 0.0f;   // pre-sequence region of segment 0

                if (s + 1 < STEPS) {
                    uint32_t boff = (uint32_t)((((ph ^ 1) * CHAINS + c) << 8)
                                               + (int)rank * 64 + j) * 4u;
                    uint32_t moff = (uint32_t)(c * 2 + (ph ^ 1)) * 8u;
                    #pragma unroll
                    for (int r = 0; r < 4; ++r)
                        st_async_f32(peer_hb[r] + boff, hn, peer_mb[r] + moff);
                }

                if (s >= WARMUP) {
                    if (enc) {
                        if ((p & 127) == 127) {
                            int t_out = p >> 7;
                            out[(size_t)t_out * H_ + rank * 64 + j] = hn;
                        }
                    } else {
                        int b = p & 127, t = p >> 7;
                        out[(size_t)(T_IN_ * H_) +
                            ((size_t)b * T_OUT_ + t) * H_ + rank * 64 + j] = hn;
                    }
                }
            }
            // proceed straight to the other chain's half-step
        }
    }

    cl_sync();   // drain before cluster teardown
}

// ============================================================
// launch
// ============================================================
extern "C" void kernel_launch(void* const* d_in, const int* in_sizes, int n_in,
                              void* d_out, int out_size)
{
    const float* x     = (const float*)d_in[0];
    const float* Wih_e = (const float*)d_in[1];
    const float* Whh_e = (const float*)d_in[2];
    const float* bih_e = (const float*)d_in[3];
    const float* bhh_e = (const float*)d_in[4];
    const float* Wih_d = (const float*)d_in[5];
    const float* Whh_d = (const float*)d_in[6];
    const float* bih_d = (const float*)d_in[7];
    const float* bhh_d = (const float*)d_in[8];
    float* out = (float*)d_out;

    dim3 ggrid(ENC_LEN / 64 + DEC_LEN / 64, G3_ / 64);  // (540, 12)
    gi_gemm<<<ggrid, 256>>>(x, Wih_e, bih_e, Wih_d, bih_d);

    gru_scan<<<(NCL_ENC + NCL_DEC) * 4, 384>>>(
        Whh_e, bhh_e, Whh_d, bhh_d, out);
}